// round 14
// baseline (speedup 1.0000x reference)
#include <cuda_runtime.h>
#include <cuda_fp16.h>
#include <math.h>
#include <stdint.h>

#define NN 50000
#define NE 800000
#define HID 128
#define HID2 256
#define STEPS 12
#define DTC 0.5f
#define NTILES 391   // ceil(NN/128)
#define GTHREADS 256

// ---- A-image layout (fp16): per 128-row tile, per 128-K chunk:
// 128 rows x 16 units; unit = 8 fp16 cols = 16B. phys unit = ku ^ (r & 7).
// Chunk = 32768 B.
__device__ __forceinline__ uint32_t img_off(int r, int ku) {
    return (((uint32_t)r << 4) + ((uint32_t)ku ^ (r & 7))) * 16u;
}

// ================= scratch =================
__device__ uint8_t g_aggimg[(size_t)NTILES * 32768];        // 12.8 MB
__device__ uint8_t g_x1img[(size_t)NTILES * 2 * 32768];     // 25.6 MB
__device__ __half  g_h16[(size_t)NN * HID];                 // 12.8 MB fp16 shadow of h
__device__ float   g_invdeg[NN];
__device__ int     g_degi[NN];
__device__ int     g_rowptr[NN + 1];
__device__ int     g_cursor[NN];
__device__ int     g_srcs[NE];
// fp16 weight images ([N][K] units, 16B-unit XOR swizzle)
__device__ uint8_t g_Wimg_in[128 * 128 * 2];   // 32 KB
__device__ uint8_t g_Wimg1[256 * 128 * 2];     // 64 KB
__device__ uint8_t g_Wimg2[128 * 256 * 2];     // 64 KB

// ================= fast math =================
__device__ __forceinline__ float fast_tanh(float x) {
    float e = __expf(2.0f * x);
    return 1.0f - __fdividef(2.0f, e + 1.0f);
}

// ================= CSR build =================
__global__ void k_zero_degi() {
    int i = blockIdx.x * blockDim.x + threadIdx.x;
    if (i < NN) g_degi[i] = 0;
}
__global__ void k_hist(const int* __restrict__ ei) {
    int e = blockIdx.x * blockDim.x + threadIdx.x;
    if (e < NE) atomicAdd(&g_degi[ei[NE + e]], 1);
}
__global__ void k_scan() {
    __shared__ int part[1024];
    const int C = (NN + 1023) / 1024;
    int t = threadIdx.x;
    int beg = t * C, end = min(beg + C, NN);
    int s = 0;
    for (int i = beg; i < end; i++) s += g_degi[i];
    part[t] = s;
    __syncthreads();
    for (int off = 1; off < 1024; off <<= 1) {
        int v = (t >= off) ? part[t - off] : 0;
        __syncthreads();
        part[t] += v;
        __syncthreads();
    }
    int run = part[t] - s;
    for (int i = beg; i < end; i++) {
        int d = g_degi[i];
        g_rowptr[i] = run;
        g_cursor[i] = run;
        g_invdeg[i] = 1.0f / (float)max(d, 1);
        run += d;
    }
    if (t == 1023) g_rowptr[NN] = NE;
}
__global__ void k_scatter(const int* __restrict__ ei) {
    int e = blockIdx.x * blockDim.x + threadIdx.x;
    if (e < NE) {
        int dst = ei[NE + e];
        int p = atomicAdd(&g_cursor[dst], 1);
        g_srcs[p] = ei[e];
    }
}

// ================= fp16 gather helper =================
__device__ __forceinline__ void add4h(float4& a, uint2 v) {
    __half2 p0 = *(__half2*)&v.x;
    __half2 p1 = *(__half2*)&v.y;
    float2 f0 = __half22float2(p0);
    float2 f1 = __half22float2(p1);
    a.x += f0.x; a.y += f0.y; a.z += f1.x; a.w += f1.y;
}

// ================= aggregation: gathers fp16 h, writes fp16 image =========
__global__ void k_aggregate(const __half* __restrict__ h16, uint8_t* __restrict__ img) {
    int node = (blockIdx.x * blockDim.x + threadIdx.x) >> 5;
    int lane = threadIdx.x & 31;
    if (node >= NN) return;
    int beg = g_rowptr[node], end = g_rowptr[node + 1];
    float4 a0 = make_float4(0.f, 0.f, 0.f, 0.f);
    float4 a1 = a0, a2 = a0, a3 = a0;
    int i = beg;
    for (; i + 3 < end; i += 4) {
        int s0 = g_srcs[i], s1 = g_srcs[i + 1], s2 = g_srcs[i + 2], s3 = g_srcs[i + 3];
        uint2 v0 = *(const uint2*)&h16[(size_t)s0 * HID + lane * 4];
        uint2 v1 = *(const uint2*)&h16[(size_t)s1 * HID + lane * 4];
        uint2 v2 = *(const uint2*)&h16[(size_t)s2 * HID + lane * 4];
        uint2 v3 = *(const uint2*)&h16[(size_t)s3 * HID + lane * 4];
        add4h(a0, v0);
        add4h(a1, v1);
        add4h(a2, v2);
        add4h(a3, v3);
    }
    for (; i < end; i++) {
        uint2 v0 = *(const uint2*)&h16[(size_t)g_srcs[i] * HID + lane * 4];
        add4h(a0, v0);
    }
    float inv = g_invdeg[node];
    float m0 = (a0.x + a1.x + a2.x + a3.x) * inv;
    float m1 = (a0.y + a1.y + a2.y + a3.y) * inv;
    float m2 = (a0.z + a1.z + a2.z + a3.z) * inv;
    float m3 = (a0.w + a1.w + a2.w + a3.w) * inv;
    ushort4 H;
    H.x = __half_as_ushort(__float2half(m0));
    H.y = __half_as_ushort(__float2half(m1));
    H.z = __half_as_ushort(__float2half(m2));
    H.w = __half_as_ushort(__float2half(m3));
    int tile = node >> 7, r = node & 127;
    *(ushort4*)(img + (size_t)tile * 32768 + img_off(r, lane >> 1) + (lane & 1) * 8) = H;
}

// ================= weight image prep (fp16) =================
__global__ void k_prepw(const float* __restrict__ W, uint8_t* __restrict__ img,
                        int K, int NOUT) {
    int idx = blockIdx.x * blockDim.x + threadIdx.x;
    if (idx >= K * NOUT) return;
    int k = idx / NOUT, n = idx % NOUT;
    int SUW = K >> 3;
    size_t unit = (size_t)n * SUW + ((k >> 3) ^ (n & 7));
    *(__half*)(img + unit * 16 + (size_t)(k & 7) * 2) = __float2half(W[idx]);
}

// ================= mma.sync / cp.async helpers =================
__device__ __forceinline__ uint32_t smem_u32(const void* p) {
    uint32_t a;
    asm("{ .reg .u64 t; cvta.to.shared.u64 t, %1; cvt.u32.u64 %0, t; }" : "=r"(a) : "l"(p));
    return a;
}
__device__ __forceinline__ void cp16(uint32_t dst, const void* src) {
    asm volatile("cp.async.cg.shared.global [%0], [%1], 16;" :: "r"(dst), "l"(src));
}
__device__ __forceinline__ void cp_commit_wait() {
    asm volatile("cp.async.commit_group;");
    asm volatile("cp.async.wait_group 0;");
}
__device__ __forceinline__ void ldmx4(uint32_t* r, uint32_t addr) {
    asm volatile("ldmatrix.sync.aligned.m8n8.x4.shared.b16 {%0,%1,%2,%3}, [%4];"
                 : "=r"(r[0]), "=r"(r[1]), "=r"(r[2]), "=r"(r[3]) : "r"(addr));
}
__device__ __forceinline__ void mma16816(float* c, const uint32_t* a, uint32_t b0, uint32_t b1) {
    asm volatile(
        "mma.sync.aligned.m16n8k16.row.col.f32.f16.f16.f32 "
        "{%0,%1,%2,%3}, {%4,%5,%6,%7}, {%8,%9}, {%0,%1,%2,%3};"
        : "+f"(c[0]), "+f"(c[1]), "+f"(c[2]), "+f"(c[3])
        : "r"(a[0]), "r"(a[1]), "r"(a[2]), "r"(a[3]), "r"(b0), "r"(b1));
}

// ================= HMMA GEMM, 256 threads x 2 CTAs/SM, plain fp16 =========
// Warp grid 4(M) x 2(N): warp tile 32 rows x 64 cols (acc 64 regs).
// EPI 0: tanh -> h(fp32)+h16 ; EPI 1: gelu -> x1 image ; EPI 2: Euler -> h+h16
template <int K, int NB, int EPI, bool AIMG>
__global__ void __launch_bounds__(GTHREADS, 2) k_mgemm(
    const void* __restrict__ Xin, const uint8_t* __restrict__ Wimg,
    const float* __restrict__ Bb, void* __restrict__ OUTv,
    __half* __restrict__ Hf,
    const float* __restrict__ clr, int ntiles)
{
    constexpr int NOUT = NB * 128;
    constexpr int NCHUNK = K / 128;
    constexpr int SUW = K / 8;
    constexpr int AUNITS = 128 * 16;   // units per chunk (16B each) = 32 KB
    extern __shared__ char smem[];
    uint4* Ah = (uint4*)smem;          // AUNITS
    uint4* Wh = Ah + AUNITS;           // NOUT*SUW units
    const uint32_t ah_b = smem_u32(Ah);
    const uint32_t wh_b = smem_u32(Wh);

    const int tid = threadIdx.x;
    const int lane = tid & 31;
    const int wid = tid >> 5;
    const int wm = wid & 3;            // 4 warps over M (32 rows each)
    const int wn = wid >> 2;           // 2 warps over N (64 cols each)
    const int r8 = lane & 7;
    const int quad = lane >> 3;
    const int g = lane >> 2;
    const int tq = lane & 3;

    for (int i = tid; i < NOUT * SUW; i += GTHREADS)
        cp16(wh_b + i * 16, (const uint4*)Wimg + i);

    float decay = 0.f;
    if (EPI == 2) decay = fmaxf(clr[0], 0.f);

    for (int tile = blockIdx.x; tile < ntiles; tile += gridDim.x) {
        const int row0 = tile * 128;
        #pragma unroll 1
        for (int nb = 0; nb < NB; nb++) {
            float acc[2][8][4];
            #pragma unroll
            for (int a = 0; a < 2; a++)
                #pragma unroll
                for (int b = 0; b < 8; b++)
                    #pragma unroll
                    for (int c = 0; c < 4; c++) acc[a][b][c] = 0.f;

            #pragma unroll 1
            for (int chunk = 0; chunk < NCHUNK; chunk++) {
                if (nb == 0) {
                    __syncthreads();
                    if (AIMG) {
                        const uint8_t* src = (const uint8_t*)Xin
                            + (size_t)tile * (NCHUNK * 32768) + (size_t)chunk * 32768;
                        #pragma unroll
                        for (int i = tid; i < AUNITS; i += GTHREADS)
                            cp16(ah_b + i * 16, src + (size_t)i * 16);
                        cp_commit_wait();
                    } else {
                        const float* X = (const float*)Xin;
                        #pragma unroll 1
                        for (int u = tid; u < AUNITS; u += GTHREADS) {
                            int r = u >> 4, ku = u & 15;
                            int gr = row0 + r;
                            float4 v0 = make_float4(0.f, 0.f, 0.f, 0.f), v1 = v0;
                            if (gr < NN) {
                                const float* xp = &X[(size_t)gr * K + chunk * 128 + ku * 8];
                                v0 = *(const float4*)xp;
                                v1 = *(const float4*)(xp + 4);
                            }
                            ushort4 H0, H1;
                            H0.x = __half_as_ushort(__float2half(v0.x));
                            H0.y = __half_as_ushort(__float2half(v0.y));
                            H0.z = __half_as_ushort(__float2half(v0.z));
                            H0.w = __half_as_ushort(__float2half(v0.w));
                            H1.x = __half_as_ushort(__float2half(v1.x));
                            H1.y = __half_as_ushort(__float2half(v1.y));
                            H1.z = __half_as_ushort(__float2half(v1.z));
                            H1.w = __half_as_ushort(__float2half(v1.w));
                            uint32_t a16 = img_off(r, ku);
                            *(ushort4*)((char*)Ah + a16) = H0;
                            *(ushort4*)((char*)Ah + a16 + 8) = H1;
                        }
                        cp_commit_wait();  // drain W copy
                    }
                    __syncthreads();
                }

                #pragma unroll
                for (int ks = 0; ks < 8; ks++) {
                    uint32_t a_hi[2][4];
                    #pragma unroll
                    for (int mt = 0; mt < 2; mt++) {
                        int row = wm * 32 + mt * 16 + r8 + (quad & 1) * 8;
                        int ku = 2 * ks + (quad >> 1);
                        ldmx4(a_hi[mt], ah_b + ((row << 4) + (ku ^ (row & 7))) * 16);
                    }
                    #pragma unroll
                    for (int nt2 = 0; nt2 < 4; nt2++) {
                        int nrow = nb * 128 + wn * 64 + nt2 * 16 + r8 + (quad >> 1) * 8;
                        int ku = chunk * 16 + 2 * ks + (quad & 1);
                        uint32_t off = ((uint32_t)nrow * SUW + (ku ^ (nrow & 7))) * 16;
                        uint32_t bh[4];
                        ldmx4(bh, wh_b + off);
                        #pragma unroll
                        for (int mt = 0; mt < 2; mt++) {
                            mma16816(acc[mt][2 * nt2 + 0], a_hi[mt], bh[0], bh[1]);
                            mma16816(acc[mt][2 * nt2 + 1], a_hi[mt], bh[2], bh[3]);
                        }
                    }
                }
            }

            // ---- epilogue: warp covers 32 rows x 64 cols ----
            #pragma unroll
            for (int mt = 0; mt < 2; mt++) {
                int rbase = row0 + wm * 32 + mt * 16 + g;
                #pragma unroll
                for (int nt = 0; nt < 8; nt++) {
                    int col = nb * 128 + wn * 64 + nt * 8 + 2 * tq;
                    float2 bb = *(const float2*)&Bb[col];
                    #pragma unroll
                    for (int half = 0; half < 2; half++) {
                        int row = rbase + half * 8;
                        if (row >= NN) continue;
                        float x0 = acc[mt][nt][2 * half + 0] + bb.x;
                        float x1 = acc[mt][nt][2 * half + 1] + bb.y;
                        if (EPI == 0) {
                            float2 o;
                            o.x = fast_tanh(x0);
                            o.y = fast_tanh(x1);
                            *(float2*)&((float*)OUTv)[(size_t)row * NOUT + col] = o;
                            __half2 hp;
                            hp.x = __float2half(o.x);
                            hp.y = __float2half(o.y);
                            *(__half2*)&Hf[(size_t)row * NOUT + col] = hp;
                        } else if (EPI == 1) {
                            const float c = 0.7071067811865475f;
                            float g0 = 0.5f * x0 * (1.f + erff(x0 * c));
                            float g1 = 0.5f * x1 * (1.f + erff(x1 * c));
                            __half2 p;
                            p.x = __float2half(g0);
                            p.y = __float2half(g1);
                            int t2 = row >> 7, r = row & 127;
                            int chunk = col >> 7, kcol = col & 127;
                            *(uint32_t*)((uint8_t*)OUTv + (size_t)t2 * 65536
                                         + (size_t)chunk * 32768
                                         + img_off(r, kcol >> 3) + (kcol & 7) * 2)
                                = *(uint32_t*)&p;
                        } else {
                            float* OUT = (float*)OUTv;
                            float2 hv = *(const float2*)&OUT[(size_t)row * NOUT + col];
                            float2 o;
                            o.x = hv.x + (fast_tanh(x0) - decay * hv.x) * DTC;
                            o.y = hv.y + (fast_tanh(x1) - decay * hv.y) * DTC;
                            *(float2*)&OUT[(size_t)row * NOUT + col] = o;
                            __half2 hp;
                            hp.x = __float2half(o.x);
                            hp.y = __float2half(o.y);
                            *(__half2*)&Hf[(size_t)row * NOUT + col] = hp;
                        }
                    }
                }
            }
        }
    }
}

// ================= launch =================
extern "C" void kernel_launch(void* const* d_in, const int* in_sizes, int n_in,
                              void* d_out, int out_size) {
    const float* gat  = (const float*)d_in[0];
    const int*   ei   = (const int*)d_in[1];
    const float* W_in = (const float*)d_in[2];
    const float* b_in = (const float*)d_in[3];
    const float* W1   = (const float*)d_in[4];
    const float* b1   = (const float*)d_in[5];
    const float* W2   = (const float*)d_in[6];
    const float* b2   = (const float*)d_in[7];
    const float* clr  = (const float*)d_in[8];
    float* h = (float*)d_out;

    uint8_t *aggimg = nullptr, *x1img = nullptr;
    uint8_t *wi_in = nullptr, *wi_1 = nullptr, *wi_2 = nullptr;
    __half* h16 = nullptr;
    cudaGetSymbolAddress((void**)&aggimg, g_aggimg);
    cudaGetSymbolAddress((void**)&x1img, g_x1img);
    cudaGetSymbolAddress((void**)&h16, g_h16);
    cudaGetSymbolAddress((void**)&wi_in, g_Wimg_in);
    cudaGetSymbolAddress((void**)&wi_1, g_Wimg1);
    cudaGetSymbolAddress((void**)&wi_2, g_Wimg2);

    int sms = 148;
    cudaDeviceGetAttribute(&sms, cudaDevAttrMultiProcessorCount, 0);

    const int SM_IN = 32768 + 32768;    // 64 KB  (A + W_in)
    const int SM_G1 = 32768 + 65536;    // 96 KB  (A + W1)
    const int SM_G2 = 32768 + 65536;    // 96 KB  (A + W2)
    cudaFuncSetAttribute(k_mgemm<128, 1, 0, false>, cudaFuncAttributeMaxDynamicSharedMemorySize, SM_IN);
    cudaFuncSetAttribute(k_mgemm<128, 2, 1, true>,  cudaFuncAttributeMaxDynamicSharedMemorySize, SM_G1);
    cudaFuncSetAttribute(k_mgemm<256, 1, 2, true>,  cudaFuncAttributeMaxDynamicSharedMemorySize, SM_G2);

    const int ntiles = NTILES;
    int grid = 2 * sms;                 // 2 CTAs per SM
    if (grid > ntiles) grid = ntiles;

    // gemm0 at launch index 3 so ncu's profiled launch is the GEMM family
    k_prepw<<<(128 * 128 + 255) / 256, 256>>>(W_in, wi_in, 128, 128);       // 0
    k_zero_degi<<<(NN + 255) / 256, 256>>>();                               // 1
    k_hist<<<(NE + 255) / 256, 256>>>(ei);                                  // 2
    k_mgemm<128, 1, 0, false><<<grid, GTHREADS, SM_IN>>>(gat, wi_in, b_in,
                                                         h, h16, clr, ntiles); // 3
    k_scan<<<1, 1024>>>();                                                  // 4
    k_scatter<<<(NE + 255) / 256, 256>>>(ei);                               // 5
    k_prepw<<<(128 * 256 + 255) / 256, 256>>>(W1, wi_1, 128, 256);          // 6
    k_prepw<<<(256 * 128 + 255) / 256, 256>>>(W2, wi_2, 256, 128);          // 7

    const int agg_blocks = (NN * 32 + 255) / 256;
    for (int s = 0; s < STEPS; s++) {
        k_aggregate<<<agg_blocks, 256>>>(h16, aggimg);
        k_mgemm<128, 2, 1, true><<<grid, GTHREADS, SM_G1>>>(aggimg, wi_1, b1, x1img, h16, clr, ntiles);
        k_mgemm<256, 1, 2, true><<<grid, GTHREADS, SM_G2>>>(x1img, wi_2, b2, h, h16, clr, ntiles);
    }
}

// round 15
// speedup vs baseline: 1.0831x; 1.0831x over previous
#include <cuda_runtime.h>
#include <cuda_fp16.h>
#include <math.h>
#include <stdint.h>

#define NN 50000
#define NE 800000
#define HID 128
#define HID2 256
#define STEPS 12
#define DTC 0.5f
#define MTILE 64
#define NTILES 782   // ceil(NN/64)
#define GTHREADS 256

// ---- A-image layout (fp16): per 64-row tile, per 128-K chunk:
// 64 rows x 16 units; unit = 8 fp16 cols = 16B. phys unit = ku ^ (r & 7).
// Chunk = 16384 B.
__device__ __forceinline__ uint32_t img_off(int r, int ku) {
    return (((uint32_t)r << 4) + ((uint32_t)ku ^ (r & 7))) * 16u;
}

// ================= scratch =================
__device__ uint8_t g_aggimg[(size_t)NTILES * 16384];        // 12.8 MB
__device__ uint8_t g_x1img[(size_t)NTILES * 2 * 16384];     // 25.6 MB
__device__ float   g_invdeg[NN];
__device__ int     g_degi[NN];
__device__ int     g_rowptr[NN + 1];
__device__ int     g_cursor[NN];
__device__ int     g_srcs[NE];
// fp16 weight images ([N][K] units, 16B-unit XOR swizzle)
__device__ uint8_t g_Wimg_in[128 * 128 * 2];   // 32 KB
__device__ uint8_t g_Wimg1[256 * 128 * 2];     // 64 KB
__device__ uint8_t g_Wimg2[128 * 256 * 2];     // 64 KB

// ================= fast math =================
__device__ __forceinline__ float fast_tanh(float x) {
    float e = __expf(2.0f * x);
    return 1.0f - __fdividef(2.0f, e + 1.0f);
}

// ================= CSR build =================
__global__ void k_zero_degi() {
    int i = blockIdx.x * blockDim.x + threadIdx.x;
    if (i < NN) g_degi[i] = 0;
}
__global__ void k_hist(const int* __restrict__ ei) {
    int e = blockIdx.x * blockDim.x + threadIdx.x;
    if (e < NE) atomicAdd(&g_degi[ei[NE + e]], 1);
}
__global__ void k_scan() {
    __shared__ int part[1024];
    const int C = (NN + 1023) / 1024;
    int t = threadIdx.x;
    int beg = t * C, end = min(beg + C, NN);
    int s = 0;
    for (int i = beg; i < end; i++) s += g_degi[i];
    part[t] = s;
    __syncthreads();
    for (int off = 1; off < 1024; off <<= 1) {
        int v = (t >= off) ? part[t - off] : 0;
        __syncthreads();
        part[t] += v;
        __syncthreads();
    }
    int run = part[t] - s;
    for (int i = beg; i < end; i++) {
        int d = g_degi[i];
        g_rowptr[i] = run;
        g_cursor[i] = run;
        g_invdeg[i] = 1.0f / (float)max(d, 1);
        run += d;
    }
    if (t == 1023) g_rowptr[NN] = NE;
}
__global__ void k_scatter(const int* __restrict__ ei) {
    int e = blockIdx.x * blockDim.x + threadIdx.x;
    if (e < NE) {
        int dst = ei[NE + e];
        int p = atomicAdd(&g_cursor[dst], 1);
        g_srcs[p] = ei[e];
    }
}

// ================= aggregation: fp32 gather, writes fp16 image ============
__global__ void k_aggregate(const float* __restrict__ h, uint8_t* __restrict__ img) {
    int node = (blockIdx.x * blockDim.x + threadIdx.x) >> 5;
    int lane = threadIdx.x & 31;
    if (node >= NN) return;
    int beg = g_rowptr[node], end = g_rowptr[node + 1];
    float4 a0 = make_float4(0.f, 0.f, 0.f, 0.f);
    float4 a1 = a0, a2 = a0, a3 = a0;
    int i = beg;
    for (; i + 3 < end; i += 4) {
        int s0 = g_srcs[i], s1 = g_srcs[i + 1], s2 = g_srcs[i + 2], s3 = g_srcs[i + 3];
        float4 v0 = *(const float4*)&h[(size_t)s0 * HID + lane * 4];
        float4 v1 = *(const float4*)&h[(size_t)s1 * HID + lane * 4];
        float4 v2 = *(const float4*)&h[(size_t)s2 * HID + lane * 4];
        float4 v3 = *(const float4*)&h[(size_t)s3 * HID + lane * 4];
        a0.x += v0.x; a0.y += v0.y; a0.z += v0.z; a0.w += v0.w;
        a1.x += v1.x; a1.y += v1.y; a1.z += v1.z; a1.w += v1.w;
        a2.x += v2.x; a2.y += v2.y; a2.z += v2.z; a2.w += v2.w;
        a3.x += v3.x; a3.y += v3.y; a3.z += v3.z; a3.w += v3.w;
    }
    for (; i < end; i++) {
        float4 v0 = *(const float4*)&h[(size_t)g_srcs[i] * HID + lane * 4];
        a0.x += v0.x; a0.y += v0.y; a0.z += v0.z; a0.w += v0.w;
    }
    float inv = g_invdeg[node];
    float m0 = (a0.x + a1.x + a2.x + a3.x) * inv;
    float m1 = (a0.y + a1.y + a2.y + a3.y) * inv;
    float m2 = (a0.z + a1.z + a2.z + a3.z) * inv;
    float m3 = (a0.w + a1.w + a2.w + a3.w) * inv;
    ushort4 H;
    H.x = __half_as_ushort(__float2half(m0));
    H.y = __half_as_ushort(__float2half(m1));
    H.z = __half_as_ushort(__float2half(m2));
    H.w = __half_as_ushort(__float2half(m3));
    int tile = node >> 6, r = node & 63;
    *(ushort4*)(img + (size_t)tile * 16384 + img_off(r, lane >> 1) + (lane & 1) * 8) = H;
}

// ================= weight image prep (fp16) =================
__global__ void k_prepw(const float* __restrict__ W, uint8_t* __restrict__ img,
                        int K, int NOUT) {
    int idx = blockIdx.x * blockDim.x + threadIdx.x;
    if (idx >= K * NOUT) return;
    int k = idx / NOUT, n = idx % NOUT;
    int SUW = K >> 3;
    size_t unit = (size_t)n * SUW + ((k >> 3) ^ (n & 7));
    *(__half*)(img + unit * 16 + (size_t)(k & 7) * 2) = __float2half(W[idx]);
}

// ================= mma.sync / cp.async helpers =================
__device__ __forceinline__ uint32_t smem_u32(const void* p) {
    uint32_t a;
    asm("{ .reg .u64 t; cvta.to.shared.u64 t, %1; cvt.u32.u64 %0, t; }" : "=r"(a) : "l"(p));
    return a;
}
__device__ __forceinline__ void cp16(uint32_t dst, const void* src) {
    asm volatile("cp.async.cg.shared.global [%0], [%1], 16;" :: "r"(dst), "l"(src));
}
__device__ __forceinline__ void cp_commit_wait() {
    asm volatile("cp.async.commit_group;");
    asm volatile("cp.async.wait_group 0;");
}
__device__ __forceinline__ void ldmx4(uint32_t* r, uint32_t addr) {
    asm volatile("ldmatrix.sync.aligned.m8n8.x4.shared.b16 {%0,%1,%2,%3}, [%4];"
                 : "=r"(r[0]), "=r"(r[1]), "=r"(r[2]), "=r"(r[3]) : "r"(addr));
}
__device__ __forceinline__ void mma16816(float* c, const uint32_t* a, uint32_t b0, uint32_t b1) {
    asm volatile(
        "mma.sync.aligned.m16n8k16.row.col.f32.f16.f16.f32 "
        "{%0,%1,%2,%3}, {%4,%5,%6,%7}, {%8,%9}, {%0,%1,%2,%3};"
        : "+f"(c[0]), "+f"(c[1]), "+f"(c[2]), "+f"(c[3])
        : "r"(a[0]), "r"(a[1]), "r"(a[2]), "r"(a[3]), "r"(b0), "r"(b1));
}

// ================= HMMA GEMM, 64-row tiles, 256 thr x 2 CTAs/SM ==========
// Warp grid 2(M) x 4(N): warp tile 32 rows x 32 cols (acc 32 regs).
// EPI 0: tanh -> h(fp32) ; EPI 1: gelu -> x1 image ; EPI 2: Euler update on h
template <int K, int NB, int EPI, bool AIMG>
__global__ void __launch_bounds__(GTHREADS, 2) k_mgemm(
    const void* __restrict__ Xin, const uint8_t* __restrict__ Wimg,
    const float* __restrict__ Bb, void* __restrict__ OUTv,
    const float* __restrict__ clr, int ntiles)
{
    constexpr int NOUT = NB * 128;
    constexpr int NCHUNK = K / 128;
    constexpr int SUW = K / 8;
    constexpr int AUNITS = MTILE * 16;   // units per chunk (16B each) = 16 KB
    extern __shared__ char smem[];
    uint4* Ah = (uint4*)smem;            // AUNITS
    uint4* Wh = Ah + AUNITS;             // NOUT*SUW units
    const uint32_t ah_b = smem_u32(Ah);
    const uint32_t wh_b = smem_u32(Wh);

    const int tid = threadIdx.x;
    const int lane = tid & 31;
    const int wid = tid >> 5;
    const int wm = wid & 1;              // 2 warps over M (32 rows each)
    const int wn = wid >> 1;             // 4 warps over N (32 cols each)
    const int r8 = lane & 7;
    const int quad = lane >> 3;
    const int g = lane >> 2;
    const int tq = lane & 3;

    for (int i = tid; i < NOUT * SUW; i += GTHREADS)
        cp16(wh_b + i * 16, (const uint4*)Wimg + i);

    float decay = 0.f;
    if (EPI == 2) decay = fmaxf(clr[0], 0.f);

    for (int tile = blockIdx.x; tile < ntiles; tile += gridDim.x) {
        const int row0 = tile * MTILE;
        #pragma unroll 1
        for (int nb = 0; nb < NB; nb++) {
            float acc[2][4][4];
            #pragma unroll
            for (int a = 0; a < 2; a++)
                #pragma unroll
                for (int b = 0; b < 4; b++)
                    #pragma unroll
                    for (int c = 0; c < 4; c++) acc[a][b][c] = 0.f;

            #pragma unroll 1
            for (int chunk = 0; chunk < NCHUNK; chunk++) {
                if (nb == 0) {
                    __syncthreads();
                    if (AIMG) {
                        const uint8_t* src = (const uint8_t*)Xin
                            + (size_t)tile * (NCHUNK * 16384) + (size_t)chunk * 16384;
                        #pragma unroll
                        for (int i = tid; i < AUNITS; i += GTHREADS)
                            cp16(ah_b + i * 16, src + (size_t)i * 16);
                        cp_commit_wait();
                    } else {
                        const float* X = (const float*)Xin;
                        #pragma unroll 1
                        for (int u = tid; u < AUNITS; u += GTHREADS) {
                            int r = u >> 4, ku = u & 15;
                            int gr = row0 + r;
                            float4 v0 = make_float4(0.f, 0.f, 0.f, 0.f), v1 = v0;
                            if (gr < NN) {
                                const float* xp = &X[(size_t)gr * K + chunk * 128 + ku * 8];
                                v0 = *(const float4*)xp;
                                v1 = *(const float4*)(xp + 4);
                            }
                            ushort4 H0, H1;
                            H0.x = __half_as_ushort(__float2half(v0.x));
                            H0.y = __half_as_ushort(__float2half(v0.y));
                            H0.z = __half_as_ushort(__float2half(v0.z));
                            H0.w = __half_as_ushort(__float2half(v0.w));
                            H1.x = __half_as_ushort(__float2half(v1.x));
                            H1.y = __half_as_ushort(__float2half(v1.y));
                            H1.z = __half_as_ushort(__float2half(v1.z));
                            H1.w = __half_as_ushort(__float2half(v1.w));
                            uint32_t a16 = img_off(r, ku);
                            *(ushort4*)((char*)Ah + a16) = H0;
                            *(ushort4*)((char*)Ah + a16 + 8) = H1;
                        }
                        cp_commit_wait();  // drain W copy
                    }
                    __syncthreads();
                }

                #pragma unroll
                for (int ks = 0; ks < 8; ks++) {
                    uint32_t a_hi[2][4];
                    #pragma unroll
                    for (int mt = 0; mt < 2; mt++) {
                        int row = wm * 32 + mt * 16 + r8 + (quad & 1) * 8;
                        int ku = 2 * ks + (quad >> 1);
                        ldmx4(a_hi[mt], ah_b + ((row << 4) + (ku ^ (row & 7))) * 16);
                    }
                    #pragma unroll
                    for (int nt2 = 0; nt2 < 2; nt2++) {
                        int nrow = nb * 128 + wn * 32 + nt2 * 16 + r8 + (quad >> 1) * 8;
                        int ku = chunk * 16 + 2 * ks + (quad & 1);
                        uint32_t off = ((uint32_t)nrow * SUW + (ku ^ (nrow & 7))) * 16;
                        uint32_t bh[4];
                        ldmx4(bh, wh_b + off);
                        #pragma unroll
                        for (int mt = 0; mt < 2; mt++) {
                            mma16816(acc[mt][2 * nt2 + 0], a_hi[mt], bh[0], bh[1]);
                            mma16816(acc[mt][2 * nt2 + 1], a_hi[mt], bh[2], bh[3]);
                        }
                    }
                }
            }

            // ---- epilogue: warp covers 32 rows x 32 cols ----
            #pragma unroll
            for (int mt = 0; mt < 2; mt++) {
                int rbase = row0 + wm * 32 + mt * 16 + g;
                #pragma unroll
                for (int nt = 0; nt < 4; nt++) {
                    int col = nb * 128 + wn * 32 + nt * 8 + 2 * tq;
                    float2 bb = *(const float2*)&Bb[col];
                    #pragma unroll
                    for (int half = 0; half < 2; half++) {
                        int row = rbase + half * 8;
                        if (row >= NN) continue;
                        float x0 = acc[mt][nt][2 * half + 0] + bb.x;
                        float x1 = acc[mt][nt][2 * half + 1] + bb.y;
                        if (EPI == 0) {
                            float2 o;
                            o.x = fast_tanh(x0);
                            o.y = fast_tanh(x1);
                            *(float2*)&((float*)OUTv)[(size_t)row * NOUT + col] = o;
                        } else if (EPI == 1) {
                            const float c = 0.7071067811865475f;
                            float g0 = 0.5f * x0 * (1.f + erff(x0 * c));
                            float g1 = 0.5f * x1 * (1.f + erff(x1 * c));
                            __half2 p;
                            p.x = __float2half(g0);
                            p.y = __float2half(g1);
                            int t2 = row >> 6, r = row & 63;
                            int chunk = col >> 7, kcol = col & 127;
                            *(uint32_t*)((uint8_t*)OUTv + (size_t)t2 * 32768
                                         + (size_t)chunk * 16384
                                         + img_off(r, kcol >> 3) + (kcol & 7) * 2)
                                = *(uint32_t*)&p;
                        } else {
                            float* OUT = (float*)OUTv;
                            float2 hv = *(const float2*)&OUT[(size_t)row * NOUT + col];
                            float2 o;
                            o.x = hv.x + (fast_tanh(x0) - decay * hv.x) * DTC;
                            o.y = hv.y + (fast_tanh(x1) - decay * hv.y) * DTC;
                            *(float2*)&OUT[(size_t)row * NOUT + col] = o;
                        }
                    }
                }
            }
        }
    }
}

// ================= launch =================
extern "C" void kernel_launch(void* const* d_in, const int* in_sizes, int n_in,
                              void* d_out, int out_size) {
    const float* gat  = (const float*)d_in[0];
    const int*   ei   = (const int*)d_in[1];
    const float* W_in = (const float*)d_in[2];
    const float* b_in = (const float*)d_in[3];
    const float* W1   = (const float*)d_in[4];
    const float* b1   = (const float*)d_in[5];
    const float* W2   = (const float*)d_in[6];
    const float* b2   = (const float*)d_in[7];
    const float* clr  = (const float*)d_in[8];
    float* h = (float*)d_out;

    uint8_t *aggimg = nullptr, *x1img = nullptr;
    uint8_t *wi_in = nullptr, *wi_1 = nullptr, *wi_2 = nullptr;
    cudaGetSymbolAddress((void**)&aggimg, g_aggimg);
    cudaGetSymbolAddress((void**)&x1img, g_x1img);
    cudaGetSymbolAddress((void**)&wi_in, g_Wimg_in);
    cudaGetSymbolAddress((void**)&wi_1, g_Wimg1);
    cudaGetSymbolAddress((void**)&wi_2, g_Wimg2);

    int sms = 148;
    cudaDeviceGetAttribute(&sms, cudaDevAttrMultiProcessorCount, 0);

    const int SM_IN = 16384 + 32768;    // 48 KB  (A + W_in)
    const int SM_G1 = 16384 + 65536;    // 80 KB  (A + W1)
    const int SM_G2 = 16384 + 65536;    // 80 KB  (A + W2)
    cudaFuncSetAttribute(k_mgemm<128, 1, 0, false>, cudaFuncAttributeMaxDynamicSharedMemorySize, SM_IN);
    cudaFuncSetAttribute(k_mgemm<128, 2, 1, true>,  cudaFuncAttributeMaxDynamicSharedMemorySize, SM_G1);
    cudaFuncSetAttribute(k_mgemm<256, 1, 2, true>,  cudaFuncAttributeMaxDynamicSharedMemorySize, SM_G2);

    const int ntiles = NTILES;
    int grid = 2 * sms;                 // 2 CTAs per SM
    if (grid > ntiles) grid = ntiles;

    // gemm0 at launch index 3 so ncu's profiled launch is the GEMM family
    k_prepw<<<(128 * 128 + 255) / 256, 256>>>(W_in, wi_in, 128, 128);       // 0
    k_zero_degi<<<(NN + 255) / 256, 256>>>();                               // 1
    k_hist<<<(NE + 255) / 256, 256>>>(ei);                                  // 2
    k_mgemm<128, 1, 0, false><<<grid, GTHREADS, SM_IN>>>(gat, wi_in, b_in,
                                                         h, clr, ntiles);   // 3
    k_scan<<<1, 1024>>>();                                                  // 4
    k_scatter<<<(NE + 255) / 256, 256>>>(ei);                               // 5
    k_prepw<<<(128 * 256 + 255) / 256, 256>>>(W1, wi_1, 128, 256);          // 6
    k_prepw<<<(256 * 128 + 255) / 256, 256>>>(W2, wi_2, 256, 128);          // 7

    const int agg_blocks = (NN * 32 + 255) / 256;
    for (int s = 0; s < STEPS; s++) {
        k_aggregate<<<agg_blocks, 256>>>(h, aggimg);
        k_mgemm<128, 2, 1, true><<<grid, GTHREADS, SM_G1>>>(aggimg, wi_1, b1, x1img, clr, ntiles);
        k_mgemm<256, 1, 2, true><<<grid, GTHREADS, SM_G2>>>(x1img, wi_2, b2, h, clr, ntiles);
    }
}

// round 16
// speedup vs baseline: 1.0919x; 1.0081x over previous
#include <cuda_runtime.h>
#include <cuda_fp16.h>
#include <math.h>
#include <stdint.h>

#define NN 50000
#define NE 800000
#define HID 128
#define HID2 256
#define STEPS 12
#define DTC 0.5f
#define MTILE 64
#define NTILES 782   // ceil(NN/64)
#define GTHREADS 256

// ---- A-image layout (fp16): per 64-row tile, per 128-K chunk:
// 64 rows x 16 units; unit = 8 fp16 cols = 16B. phys unit = ku ^ (r & 7).
// Chunk = 16384 B.
__device__ __forceinline__ uint32_t img_off(int r, int ku) {
    return (((uint32_t)r << 4) + ((uint32_t)ku ^ (r & 7))) * 16u;
}

// ================= scratch =================
__device__ uint8_t g_aggimg[(size_t)NTILES * 16384];        // 12.8 MB
__device__ uint8_t g_x1img[(size_t)NTILES * 2 * 16384];     // 25.6 MB
__device__ float   g_invdeg[NN];
__device__ int     g_degi[NN];
__device__ int     g_rowptr[NN + 1];
__device__ int     g_cursor[NN];
__device__ int     g_srcs[NE];
// fp16 weight images ([N][K] units, 16B-unit XOR swizzle)
__device__ uint8_t g_Wimg_in[128 * 128 * 2];   // 32 KB
__device__ uint8_t g_Wimg1[256 * 128 * 2];     // 64 KB
__device__ uint8_t g_Wimg2[128 * 256 * 2];     // 64 KB

// ================= fast math =================
__device__ __forceinline__ float fast_tanh(float x) {
    float e = __expf(2.0f * x);
    return 1.0f - __fdividef(2.0f, e + 1.0f);
}

// ================= CSR build =================
__global__ void k_zero_degi() {
    int i = blockIdx.x * blockDim.x + threadIdx.x;
    if (i < NN) g_degi[i] = 0;
}
__global__ void k_hist(const int* __restrict__ ei) {
    int e = blockIdx.x * blockDim.x + threadIdx.x;
    if (e < NE) atomicAdd(&g_degi[ei[NE + e]], 1);
}
__global__ void k_scan() {
    __shared__ int part[1024];
    const int C = (NN + 1023) / 1024;
    int t = threadIdx.x;
    int beg = t * C, end = min(beg + C, NN);
    int s = 0;
    for (int i = beg; i < end; i++) s += g_degi[i];
    part[t] = s;
    __syncthreads();
    for (int off = 1; off < 1024; off <<= 1) {
        int v = (t >= off) ? part[t - off] : 0;
        __syncthreads();
        part[t] += v;
        __syncthreads();
    }
    int run = part[t] - s;
    for (int i = beg; i < end; i++) {
        int d = g_degi[i];
        g_rowptr[i] = run;
        g_cursor[i] = run;
        g_invdeg[i] = 1.0f / (float)max(d, 1);
        run += d;
    }
    if (t == 1023) g_rowptr[NN] = NE;
}
__global__ void k_scatter(const int* __restrict__ ei) {
    int e = blockIdx.x * blockDim.x + threadIdx.x;
    if (e < NE) {
        int dst = ei[NE + e];
        int p = atomicAdd(&g_cursor[dst], 1);
        g_srcs[p] = ei[e];
    }
}

// ================= aggregation: fp32 gather, writes fp16 image ============
__global__ void k_aggregate(const float* __restrict__ h, uint8_t* __restrict__ img) {
    int node = (blockIdx.x * blockDim.x + threadIdx.x) >> 5;
    int lane = threadIdx.x & 31;
    if (node >= NN) return;
    int beg = g_rowptr[node], end = g_rowptr[node + 1];
    float4 a0 = make_float4(0.f, 0.f, 0.f, 0.f);
    float4 a1 = a0, a2 = a0, a3 = a0;
    int i = beg;
    for (; i + 3 < end; i += 4) {
        int s0 = g_srcs[i], s1 = g_srcs[i + 1], s2 = g_srcs[i + 2], s3 = g_srcs[i + 3];
        float4 v0 = *(const float4*)&h[(size_t)s0 * HID + lane * 4];
        float4 v1 = *(const float4*)&h[(size_t)s1 * HID + lane * 4];
        float4 v2 = *(const float4*)&h[(size_t)s2 * HID + lane * 4];
        float4 v3 = *(const float4*)&h[(size_t)s3 * HID + lane * 4];
        a0.x += v0.x; a0.y += v0.y; a0.z += v0.z; a0.w += v0.w;
        a1.x += v1.x; a1.y += v1.y; a1.z += v1.z; a1.w += v1.w;
        a2.x += v2.x; a2.y += v2.y; a2.z += v2.z; a2.w += v2.w;
        a3.x += v3.x; a3.y += v3.y; a3.z += v3.z; a3.w += v3.w;
    }
    for (; i < end; i++) {
        float4 v0 = *(const float4*)&h[(size_t)g_srcs[i] * HID + lane * 4];
        a0.x += v0.x; a0.y += v0.y; a0.z += v0.z; a0.w += v0.w;
    }
    float inv = g_invdeg[node];
    float m0 = (a0.x + a1.x + a2.x + a3.x) * inv;
    float m1 = (a0.y + a1.y + a2.y + a3.y) * inv;
    float m2 = (a0.z + a1.z + a2.z + a3.z) * inv;
    float m3 = (a0.w + a1.w + a2.w + a3.w) * inv;
    ushort4 H;
    H.x = __half_as_ushort(__float2half(m0));
    H.y = __half_as_ushort(__float2half(m1));
    H.z = __half_as_ushort(__float2half(m2));
    H.w = __half_as_ushort(__float2half(m3));
    int tile = node >> 6, r = node & 63;
    *(ushort4*)(img + (size_t)tile * 16384 + img_off(r, lane >> 1) + (lane & 1) * 8) = H;
}

// ================= weight image prep (fp16) =================
__global__ void k_prepw(const float* __restrict__ W, uint8_t* __restrict__ img,
                        int K, int NOUT) {
    int idx = blockIdx.x * blockDim.x + threadIdx.x;
    if (idx >= K * NOUT) return;
    int k = idx / NOUT, n = idx % NOUT;
    int SUW = K >> 3;
    size_t unit = (size_t)n * SUW + ((k >> 3) ^ (n & 7));
    *(__half*)(img + unit * 16 + (size_t)(k & 7) * 2) = __float2half(W[idx]);
}

// ================= mma.sync / cp.async helpers =================
__device__ __forceinline__ uint32_t smem_u32(const void* p) {
    uint32_t a;
    asm("{ .reg .u64 t; cvta.to.shared.u64 t, %1; cvt.u32.u64 %0, t; }" : "=r"(a) : "l"(p));
    return a;
}
__device__ __forceinline__ void cp16(uint32_t dst, const void* src) {
    asm volatile("cp.async.cg.shared.global [%0], [%1], 16;" :: "r"(dst), "l"(src));
}
__device__ __forceinline__ void cp_commit() {
    asm volatile("cp.async.commit_group;");
}
__device__ __forceinline__ void cp_wait0() {
    asm volatile("cp.async.wait_group 0;");
}
__device__ __forceinline__ void cp_wait1() {
    asm volatile("cp.async.wait_group 1;");
}
__device__ __forceinline__ void ldmx4(uint32_t* r, uint32_t addr) {
    asm volatile("ldmatrix.sync.aligned.m8n8.x4.shared.b16 {%0,%1,%2,%3}, [%4];"
                 : "=r"(r[0]), "=r"(r[1]), "=r"(r[2]), "=r"(r[3]) : "r"(addr));
}
__device__ __forceinline__ void mma16816(float* c, const uint32_t* a, uint32_t b0, uint32_t b1) {
    asm volatile(
        "mma.sync.aligned.m16n8k16.row.col.f32.f16.f16.f32 "
        "{%0,%1,%2,%3}, {%4,%5,%6,%7}, {%8,%9}, {%0,%1,%2,%3};"
        : "+f"(c[0]), "+f"(c[1]), "+f"(c[2]), "+f"(c[3])
        : "r"(a[0]), "r"(a[1]), "r"(a[2]), "r"(a[3]), "r"(b0), "r"(b1));
}

// ================= HMMA GEMM, 64-row tiles, 2 CTAs/SM, A double-buffered ==
// Warp grid 2(M) x 4(N): warp tile 32 rows x 32 cols (acc 32 regs).
// AIMG=true: A chunks stream via cp.async double buffer (prefetch next while
// computing current; wait_group 1 keeps one prefetch in flight).
// EPI 0: tanh -> h(fp32) ; EPI 1: gelu -> x1 image ; EPI 2: Euler update on h
template <int K, int NB, int EPI, bool AIMG>
__global__ void __launch_bounds__(GTHREADS, 2) k_mgemm(
    const void* __restrict__ Xin, const uint8_t* __restrict__ Wimg,
    const float* __restrict__ Bb, void* __restrict__ OUTv,
    const float* __restrict__ clr, int ntiles)
{
    constexpr int NOUT = NB * 128;
    constexpr int NCHUNK = K / 128;
    constexpr int SUW = K / 8;
    constexpr int AUNITS = MTILE * 16;     // 1024 units = 16 KB per chunk
    constexpr int CHUNKB = AUNITS * 16;    // 16384 bytes
    extern __shared__ char smem[];
    uint4* Ah = (uint4*)smem;              // 1 or 2 chunk buffers
    uint4* Wh = Ah + (AIMG ? 2 : 1) * AUNITS;
    const uint32_t ah_b = smem_u32(Ah);
    const uint32_t wh_b = smem_u32(Wh);
    const uint32_t abase[2] = { ah_b, ah_b + (AIMG ? CHUNKB : 0) };

    const int tid = threadIdx.x;
    const int lane = tid & 31;
    const int wid = tid >> 5;
    const int wm = wid & 1;                // 2 warps over M (32 rows each)
    const int wn = wid >> 1;               // 4 warps over N (32 cols each)
    const int r8 = lane & 7;
    const int quad = lane >> 3;
    const int g = lane >> 2;
    const int tq = lane & 3;

    for (int i = tid; i < NOUT * SUW; i += GTHREADS)
        cp16(wh_b + i * 16, (const uint4*)Wimg + i);

    float decay = 0.f;
    if (EPI == 2) decay = fmaxf(clr[0], 0.f);

    // pipeline state (AIMG only): (pt, pc) = next stream element to prefetch
    int p = 0;
    int pt = blockIdx.x, pc = 0;
    if (AIMG) {
        // prologue: prefetch first stream element into buf0 (same group as W)
        const uint8_t* src = (const uint8_t*)Xin
            + (size_t)pt * (NCHUNK * CHUNKB);
        #pragma unroll
        for (int i = tid; i < AUNITS; i += GTHREADS)
            cp16(abase[0] + i * 16, src + (size_t)i * 16);
        cp_commit();
        if (++pc == NCHUNK) { pc = 0; pt += gridDim.x; }
    }

    for (int tile = blockIdx.x; tile < ntiles; tile += gridDim.x) {
        const int row0 = tile * MTILE;
        int bufc[NCHUNK];                  // buffer index holding each chunk
        #pragma unroll 1
        for (int nb = 0; nb < NB; nb++) {
            float acc[2][4][4];
            #pragma unroll
            for (int a = 0; a < 2; a++)
                #pragma unroll
                for (int b = 0; b < 4; b++)
                    #pragma unroll
                    for (int c = 0; c < 4; c++) acc[a][b][c] = 0.f;

            #pragma unroll 1
            for (int chunk = 0; chunk < NCHUNK; chunk++) {
                if (nb == 0) {
                    if (AIMG) {
                        __syncthreads();       // prior readers of buf[p^1] done
                        // prefetch next stream element into buf[p^1]
                        if (pt < ntiles) {
                            const uint8_t* src = (const uint8_t*)Xin
                                + (size_t)pt * (NCHUNK * CHUNKB) + (size_t)pc * CHUNKB;
                            #pragma unroll
                            for (int i = tid; i < AUNITS; i += GTHREADS)
                                cp16(abase[p ^ 1] + i * 16, src + (size_t)i * 16);
                        }
                        cp_commit();
                        cp_wait1();            // buf[p] (current chunk) ready
                        __syncthreads();
                        bufc[chunk] = p;
                        p ^= 1;
                        if (++pc == NCHUNK) { pc = 0; pt += gridDim.x; }
                    } else {
                        __syncthreads();
                        const float* X = (const float*)Xin;
                        #pragma unroll 1
                        for (int u = tid; u < AUNITS; u += GTHREADS) {
                            int r = u >> 4, ku = u & 15;
                            int gr = row0 + r;
                            float4 v0 = make_float4(0.f, 0.f, 0.f, 0.f), v1 = v0;
                            if (gr < NN) {
                                const float* xp = &X[(size_t)gr * K + chunk * 128 + ku * 8];
                                v0 = *(const float4*)xp;
                                v1 = *(const float4*)(xp + 4);
                            }
                            ushort4 H0, H1;
                            H0.x = __half_as_ushort(__float2half(v0.x));
                            H0.y = __half_as_ushort(__float2half(v0.y));
                            H0.z = __half_as_ushort(__float2half(v0.z));
                            H0.w = __half_as_ushort(__float2half(v0.w));
                            H1.x = __half_as_ushort(__float2half(v1.x));
                            H1.y = __half_as_ushort(__float2half(v1.y));
                            H1.z = __half_as_ushort(__float2half(v1.z));
                            H1.w = __half_as_ushort(__float2half(v1.w));
                            uint32_t a16 = img_off(r, ku);
                            *(ushort4*)((char*)Ah + a16) = H0;
                            *(ushort4*)((char*)Ah + a16 + 8) = H1;
                        }
                        cp_wait0();            // drain W copy
                        __syncthreads();
                        bufc[chunk] = 0;
                    }
                }

                const uint32_t ab = abase[bufc[chunk]];
                #pragma unroll
                for (int ks = 0; ks < 8; ks++) {
                    uint32_t a_hi[2][4];
                    #pragma unroll
                    for (int mt = 0; mt < 2; mt++) {
                        int row = wm * 32 + mt * 16 + r8 + (quad & 1) * 8;
                        int ku = 2 * ks + (quad >> 1);
                        ldmx4(a_hi[mt], ab + ((row << 4) + (ku ^ (row & 7))) * 16);
                    }
                    #pragma unroll
                    for (int nt2 = 0; nt2 < 2; nt2++) {
                        int nrow = nb * 128 + wn * 32 + nt2 * 16 + r8 + (quad >> 1) * 8;
                        int ku = chunk * 16 + 2 * ks + (quad & 1);
                        uint32_t off = ((uint32_t)nrow * SUW + (ku ^ (nrow & 7))) * 16;
                        uint32_t bh[4];
                        ldmx4(bh, wh_b + off);
                        #pragma unroll
                        for (int mt = 0; mt < 2; mt++) {
                            mma16816(acc[mt][2 * nt2 + 0], a_hi[mt], bh[0], bh[1]);
                            mma16816(acc[mt][2 * nt2 + 1], a_hi[mt], bh[2], bh[3]);
                        }
                    }
                }
            }

            // ---- epilogue: warp covers 32 rows x 32 cols ----
            #pragma unroll
            for (int mt = 0; mt < 2; mt++) {
                int rbase = row0 + wm * 32 + mt * 16 + g;
                #pragma unroll
                for (int nt = 0; nt < 4; nt++) {
                    int col = nb * 128 + wn * 32 + nt * 8 + 2 * tq;
                    float2 bb = *(const float2*)&Bb[col];
                    #pragma unroll
                    for (int half = 0; half < 2; half++) {
                        int row = rbase + half * 8;
                        if (row >= NN) continue;
                        float x0 = acc[mt][nt][2 * half + 0] + bb.x;
                        float x1 = acc[mt][nt][2 * half + 1] + bb.y;
                        if (EPI == 0) {
                            float2 o;
                            o.x = fast_tanh(x0);
                            o.y = fast_tanh(x1);
                            *(float2*)&((float*)OUTv)[(size_t)row * NOUT + col] = o;
                        } else if (EPI == 1) {
                            const float c = 0.7071067811865475f;
                            float g0 = 0.5f * x0 * (1.f + erff(x0 * c));
                            float g1 = 0.5f * x1 * (1.f + erff(x1 * c));
                            __half2 pk;
                            pk.x = __float2half(g0);
                            pk.y = __float2half(g1);
                            int t2 = row >> 6, r = row & 63;
                            int ch = col >> 7, kcol = col & 127;
                            *(uint32_t*)((uint8_t*)OUTv + (size_t)t2 * 32768
                                         + (size_t)ch * 16384
                                         + img_off(r, kcol >> 3) + (kcol & 7) * 2)
                                = *(uint32_t*)&pk;
                        } else {
                            float* OUT = (float*)OUTv;
                            float2 hv = *(const float2*)&OUT[(size_t)row * NOUT + col];
                            float2 o;
                            o.x = hv.x + (fast_tanh(x0) - decay * hv.x) * DTC;
                            o.y = hv.y + (fast_tanh(x1) - decay * hv.y) * DTC;
                            *(float2*)&OUT[(size_t)row * NOUT + col] = o;
                        }
                    }
                }
            }
        }
    }
    if (AIMG) cp_wait0();   // drain trailing prefetch before exit
}

// ================= launch =================
extern "C" void kernel_launch(void* const* d_in, const int* in_sizes, int n_in,
                              void* d_out, int out_size) {
    const float* gat  = (const float*)d_in[0];
    const int*   ei   = (const int*)d_in[1];
    const float* W_in = (const float*)d_in[2];
    const float* b_in = (const float*)d_in[3];
    const float* W1   = (const float*)d_in[4];
    const float* b1   = (const float*)d_in[5];
    const float* W2   = (const float*)d_in[6];
    const float* b2   = (const float*)d_in[7];
    const float* clr  = (const float*)d_in[8];
    float* h = (float*)d_out;

    uint8_t *aggimg = nullptr, *x1img = nullptr;
    uint8_t *wi_in = nullptr, *wi_1 = nullptr, *wi_2 = nullptr;
    cudaGetSymbolAddress((void**)&aggimg, g_aggimg);
    cudaGetSymbolAddress((void**)&x1img, g_x1img);
    cudaGetSymbolAddress((void**)&wi_in, g_Wimg_in);
    cudaGetSymbolAddress((void**)&wi_1, g_Wimg1);
    cudaGetSymbolAddress((void**)&wi_2, g_Wimg2);

    int sms = 148;
    cudaDeviceGetAttribute(&sms, cudaDevAttrMultiProcessorCount, 0);

    const int SM_IN = 16384 + 32768;            // 48 KB (A + W_in)
    const int SM_G1 = 2 * 16384 + 65536;        // 96 KB (A x2 + W1)
    const int SM_G2 = 2 * 16384 + 65536;        // 96 KB (A x2 + W2)
    cudaFuncSetAttribute(k_mgemm<128, 1, 0, false>, cudaFuncAttributeMaxDynamicSharedMemorySize, SM_IN);
    cudaFuncSetAttribute(k_mgemm<128, 2, 1, true>,  cudaFuncAttributeMaxDynamicSharedMemorySize, SM_G1);
    cudaFuncSetAttribute(k_mgemm<256, 1, 2, true>,  cudaFuncAttributeMaxDynamicSharedMemorySize, SM_G2);

    const int ntiles = NTILES;
    int grid = 2 * sms;                 // 2 CTAs per SM
    if (grid > ntiles) grid = ntiles;

    // gemm0 at launch index 3 so ncu's profiled launch is the GEMM family
    k_prepw<<<(128 * 128 + 255) / 256, 256>>>(W_in, wi_in, 128, 128);       // 0
    k_zero_degi<<<(NN + 255) / 256, 256>>>();                               // 1
    k_hist<<<(NE + 255) / 256, 256>>>(ei);                                  // 2
    k_mgemm<128, 1, 0, false><<<grid, GTHREADS, SM_IN>>>(gat, wi_in, b_in,
                                                         h, clr, ntiles);   // 3
    k_scan<<<1, 1024>>>();                                                  // 4
    k_scatter<<<(NE + 255) / 256, 256>>>(ei);                               // 5
    k_prepw<<<(128 * 256 + 255) / 256, 256>>>(W1, wi_1, 128, 256);          // 6
    k_prepw<<<(256 * 128 + 255) / 256, 256>>>(W2, wi_2, 256, 128);          // 7

    const int agg_blocks = (NN * 32 + 255) / 256;
    for (int s = 0; s < STEPS; s++) {
        k_aggregate<<<agg_blocks, 256>>>(h, aggimg);
        k_mgemm<128, 2, 1, true><<<grid, GTHREADS, SM_G1>>>(aggimg, wi_1, b1, x1img, clr, ntiles);
        k_mgemm<256, 1, 2, true><<<grid, GTHREADS, SM_G2>>>(x1img, wi_2, b2, h, clr, ntiles);
    }
}